// round 10
// baseline (speedup 1.0000x reference)
#include <cuda_runtime.h>
#include <cuda_bf16.h>
#include <math.h>
#include <stdint.h>

// Problem constants: N=64, T=512, D=512, H=512, fp32
#define NB   64
#define TT   512
#define DD   512
#define HH   512
#define MM   (NB * TT)

// ---------------------------------------------------------------------------
// f32x2 packed-math helpers
// ---------------------------------------------------------------------------
__device__ __forceinline__ void ffma2(unsigned long long& acc,
                                      unsigned long long a,
                                      unsigned long long b) {
    asm("fma.rn.f32x2 %0, %1, %2, %0;" : "+l"(acc) : "l"(a), "l"(b));
}
__device__ __forceinline__ unsigned long long add2(unsigned long long a,
                                                   unsigned long long b) {
    unsigned long long r;
    asm("add.rn.f32x2 %0, %1, %2;" : "=l"(r) : "l"(a), "l"(b));
    return r;
}
__device__ __forceinline__ unsigned long long pack_dup(float v) {
    unsigned long long r;
    unsigned u = __float_as_uint(v);
    asm("mov.b64 %0, {%1, %1};" : "=l"(r) : "r"(u));
    return r;
}
__device__ __forceinline__ unsigned long long pack2(float lo, float hi) {
    unsigned long long r;
    asm("mov.b64 %0, {%1, %2};" : "=l"(r) : "f"(lo), "f"(hi));
    return r;
}

// mbarrier helpers -----------------------------------------------------------
#define MBAR_INIT(addr, cnt) \
    asm volatile("mbarrier.init.shared.b64 [%0], %1;" :: "r"(addr), "r"(cnt) : "memory")
#define MBAR_EXPECT_TX(addr, bytes) \
    asm volatile("mbarrier.arrive.expect_tx.shared.b64 _, [%0], %1;" \
                 :: "r"(addr), "r"(bytes) : "memory")
#define MBAR_ARRIVE_REMOTE(addr) \
    asm volatile("mbarrier.arrive.shared::cluster.b64 _, [%0];" :: "r"(addr) : "memory")

__device__ __forceinline__ void mbar_wait_parity(uint32_t mbar, uint32_t parity) {
    asm volatile(
        "{\n\t"
        ".reg .pred P;\n\t"
        "WL_%=:\n\t"
        "mbarrier.try_wait.parity.acquire.cluster.shared::cta.b64 P, [%0], %1, 0x989680;\n\t"
        "@P bra WD_%=;\n\t"
        "bra WL_%=;\n\t"
        "WD_%=:\n\t"
        "}" :: "r"(mbar), "r"(parity) : "memory");
}

__device__ __forceinline__ void st_async_b64(uint32_t raddr, unsigned long long v,
                                             uint32_t rmbar) {
    asm volatile(
        "st.async.shared::cluster.mbarrier::complete_tx::bytes.b64 [%0], %1, [%2];"
        :: "r"(raddr), "l"(v), "r"(rmbar) : "memory");
}

__device__ __forceinline__ unsigned long long shfl_down16_b64(unsigned long long v) {
    unsigned lo = (unsigned)(v & 0xFFFFFFFFULL);
    unsigned hi = (unsigned)(v >> 32);
    lo = __shfl_down_sync(0xFFFFFFFFu, lo, 16);
    hi = __shfl_down_sync(0xFFFFFFFFu, hi, 16);
    return ((unsigned long long)hi << 32) | lo;
}

// ---------------------------------------------------------------------------
// Kernel A: xwx = x @ Wx + b  (into d_out), FFMA2 SGEMM (unchanged)
// ---------------------------------------------------------------------------
#define BM 128
#define BN 128
#define BK 8

__global__ __launch_bounds__(256) void gemm_xwx_kernel(
    const float* __restrict__ X,
    const float* __restrict__ Wx,
    const float* __restrict__ bias,
    float* __restrict__ out)
{
    __shared__ float2 Asd[BK][BM];
    __shared__ float  Bs[BK][BN];

    const int tid = threadIdx.x;
    const int m0 = blockIdx.y * BM;
    const int n0 = blockIdx.x * BN;

    const int arow = tid >> 1;
    const int acol = (tid & 1) * 4;
    const int brow = tid >> 5;
    const int bcol = (tid & 31) * 4;

    const int ty = tid >> 4;
    const int tx = tid & 15;

    unsigned long long acc2[8][4];
#pragma unroll
    for (int i = 0; i < 8; ++i)
#pragma unroll
        for (int j = 0; j < 4; ++j) acc2[i][j] = 0ULL;

    for (int k0 = 0; k0 < DD; k0 += BK) {
        float4 av = *reinterpret_cast<const float4*>(
            X + (size_t)(m0 + arow) * DD + k0 + acol);
        float4 bv = *reinterpret_cast<const float4*>(
            Wx + (size_t)(k0 + brow) * HH + n0 + bcol);

        Asd[acol + 0][arow] = make_float2(av.x, av.x);
        Asd[acol + 1][arow] = make_float2(av.y, av.y);
        Asd[acol + 2][arow] = make_float2(av.z, av.z);
        Asd[acol + 3][arow] = make_float2(av.w, av.w);
        *reinterpret_cast<float4*>(&Bs[brow][bcol]) = bv;
        __syncthreads();

#pragma unroll
        for (int k = 0; k < BK; ++k) {
            unsigned long long a2[8], b2[4];
            ulonglong2 t0 = *reinterpret_cast<const ulonglong2*>(&Bs[k][tx * 8]);
            ulonglong2 t1 = *reinterpret_cast<const ulonglong2*>(&Bs[k][tx * 8 + 4]);
            b2[0] = t0.x; b2[1] = t0.y; b2[2] = t1.x; b2[3] = t1.y;
#pragma unroll
            for (int i = 0; i < 8; ++i)
                a2[i] = *reinterpret_cast<const unsigned long long*>(&Asd[k][ty * 8 + i]);
#pragma unroll
            for (int i = 0; i < 8; ++i)
#pragma unroll
                for (int j = 0; j < 4; ++j)
                    ffma2(acc2[i][j], a2[i], b2[j]);
        }
        __syncthreads();
    }

    unsigned long long bb2[4];
    {
        ulonglong2 t0 = *reinterpret_cast<const ulonglong2*>(bias + n0 + tx * 8);
        ulonglong2 t1 = *reinterpret_cast<const ulonglong2*>(bias + n0 + tx * 8 + 4);
        bb2[0] = t0.x; bb2[1] = t0.y; bb2[2] = t1.x; bb2[3] = t1.y;
    }
#pragma unroll
    for (int i = 0; i < 8; ++i) {
        float* orow = out + (size_t)(m0 + ty * 8 + i) * HH + n0 + tx * 8;
        ulonglong2 v0, v1;
        v0.x = add2(acc2[i][0], bb2[0]);
        v0.y = add2(acc2[i][1], bb2[1]);
        v1.x = add2(acc2[i][2], bb2[2]);
        v1.y = add2(acc2[i][3], bb2[3]);
        *reinterpret_cast<ulonglong2*>(orow)     = v0;
        *reinterpret_cast<ulonglong2*>(orow + 4) = v1;
    }
}

// ---------------------------------------------------------------------------
// Kernel B: cluster recurrence.
//   NEW vs R8:
//   (1) warp shfl pre-reduce: lane L += lane L+16 (adjacent kq, same cols)
//       -> 16 partials instead of 32; half the STS; reduce LDS 32 -> 16.
//   (2) red double-buffered (16 KB x2) -> trailing __syncthreads deleted;
//       ONE block barrier per step. Safety: reduce-read(t-1) < bar(t) <
//       STS(t+1) for every thread, so red[p'] never races across steps.
// ---------------------------------------------------------------------------
#define CLUSTER       8
#define NCTA          128
#define BATCH_PER_CL  4
#define COLS_PER_CTA  64

#define HBUF_ELEMS  (2 * BATCH_PER_CL * HH)              // 4096 floats (16 KB)
#define RED16_ELEMS (16 * BATCH_PER_CL * COLS_PER_CTA)   // 4096 floats (16 KB)
#define MBAR_OFF    ((HBUF_ELEMS + 2 * RED16_ELEMS) * 4) // 49152 bytes
// mbar layout: full[2][8] at +0..128 (stride 8), empty[2] at +128, +136
#define MB_FULL(p, r) (MBAR_OFF + ((p) * 8 + (r)) * 8)
#define MB_EMPTY(p)   (MBAR_OFF + 128 + (p) * 8)
#define RNN_SMEM_BYTES (MBAR_OFF + 160)

#define CHUNK_TX_BYTES 1024   // 128 producer threads x 8 B land per peer chunk

__global__ __launch_bounds__(512, 1) __cluster_dims__(CLUSTER, 1, 1)
void rnn_cluster_kernel(const float* __restrict__ h0,
                        const float* __restrict__ Wh,
                        float* __restrict__ out)
{
    extern __shared__ float smem[];
    float* hbuf = smem;                       // [2][4][HH]
    float* red  = smem + HBUF_ELEMS;          // [2][16][4][64]

    const int tid = threadIdx.x;
    uint32_t rank;
    asm("mov.u32 %0, %%cluster_ctarank;" : "=r"(rank));
    const int cid = blockIdx.x >> 3;
    const int b0  = cid * BATCH_PER_CL;

    const int kq    = tid >> 4;          // 0..31
    const int cq    = tid & 15;          // 0..15
    const int kbase = kq * 16;
    const int kq2   = tid >> 5;          // warp id 0..15 (pre-reduced partial idx)
    const int chunk = tid >> 6;          // 0..7: source rank my warp consumes
    const int jg0   = (int)rank * COLS_PER_CTA + cq * 4;

    // ---- Wh slice -> registers (once) ----
    unsigned long long w01[16], w23[16];
#pragma unroll
    for (int kk = 0; kk < 16; ++kk) {
        ulonglong2 v = *reinterpret_cast<const ulonglong2*>(
            Wh + (size_t)(kbase + kk) * HH + jg0);
        w01[kk] = v.x;
        w23[kk] = v.y;
    }

    uint32_t smem_u32;
    asm("{ .reg .u64 t; cvta.to.shared.u64 t, %1; cvt.u32.u64 %0, t; }"
        : "=r"(smem_u32) : "l"(smem));

    // ---- init: mbarriers + h0 into buffer 0 ----
    if (tid == 0) {
#pragma unroll
        for (int r = 0; r < CLUSTER; ++r) {
            MBAR_INIT(smem_u32 + MB_FULL(0, r), 1);
            MBAR_INIT(smem_u32 + MB_FULL(1, r), 1);
            MBAR_EXPECT_TX(smem_u32 + MB_FULL(0, r), CHUNK_TX_BYTES);
            MBAR_EXPECT_TX(smem_u32 + MB_FULL(1, r), CHUNK_TX_BYTES);
        }
        MBAR_INIT(smem_u32 + MB_EMPTY(0), CLUSTER);
        MBAR_INIT(smem_u32 + MB_EMPTY(1), CLUSTER);
    }
    for (int idx = tid; idx < BATCH_PER_CL * HH; idx += 512)
        hbuf[idx] = h0[(size_t)b0 * HH + idx];
    __syncthreads();
    asm volatile("barrier.cluster.arrive.aligned;\n\t"
                 "barrier.cluster.wait.aligned;" ::: "memory");

    // peer smem base addresses (mapa once)
    uint32_t rbase[CLUSTER];
#pragma unroll
    for (int p = 0; p < CLUSTER; ++p)
        asm("mapa.shared::cluster.u32 %0, %1, %2;"
            : "=r"(rbase[p]) : "r"(smem_u32), "r"(p));

    // output-stage mapping (threads < 256)
    const int fb = (tid >> 6) & 3;
    const int fc = tid & 63;
    const int jg = (int)rank * COLS_PER_CTA + fc;
    float* outp = out + ((size_t)(b0 + fb) * TT) * HH + jg;
    const bool is_red   = (tid < 256);
    const bool is_store = (tid < 256) && ((tid & 1) == 0);
    const bool is_hk    = (tid < CLUSTER);   // housekeeping thread (one per rank)
    const bool is_lo    = ((tid & 16) == 0); // lane < 16 within warp

    int pf[2] = {0, 0};   // per-warp parity for full[buf][chunk]
    int pe[2] = {0, 0};   // producer parity for empty[buf]

#pragma unroll 2
    for (int t = 0; t < TT; ++t) {
        const int p = t & 1;
        const int q = p ^ 1;

        // prefetch xwx for this step (independent of h)
        float xw = 0.0f;
        if (is_red) xw = outp[(size_t)t * HH];

        // wait only for MY chunk of h_t (produced by CTA `chunk`)
        if (t > 0) {
            mbar_wait_parity(smem_u32 + MB_FULL(p, chunk), (uint32_t)pf[p]);
            pf[p] ^= 1;
        }

        const float* hc = hbuf + p * (BATCH_PER_CL * HH);
        unsigned long long a01[4] = {0ULL, 0ULL, 0ULL, 0ULL};
        unsigned long long a23[4] = {0ULL, 0ULL, 0ULL, 0ULL};

#pragma unroll
        for (int kk4 = 0; kk4 < 4; ++kk4) {
            const int k = kbase + kk4 * 4;
#pragma unroll
            for (int b = 0; b < 4; ++b) {
                float4 hv = *reinterpret_cast<const float4*>(&hc[b * HH + k]);
                unsigned long long hh;
                hh = pack_dup(hv.x);
                ffma2(a01[b], hh, w01[kk4 * 4 + 0]);
                ffma2(a23[b], hh, w23[kk4 * 4 + 0]);
                hh = pack_dup(hv.y);
                ffma2(a01[b], hh, w01[kk4 * 4 + 1]);
                ffma2(a23[b], hh, w23[kk4 * 4 + 1]);
                hh = pack_dup(hv.z);
                ffma2(a01[b], hh, w01[kk4 * 4 + 2]);
                ffma2(a23[b], hh, w23[kk4 * 4 + 2]);
                hh = pack_dup(hv.w);
                ffma2(a01[b], hh, w01[kk4 * 4 + 3]);
                ffma2(a23[b], hh, w23[kk4 * 4 + 3]);
            }
        }

        // warp pre-reduce: lane L += lane L+16 (kq pair, same cols)
#pragma unroll
        for (int b = 0; b < 4; ++b) {
            a01[b] = add2(a01[b], shfl_down16_b64(a01[b]));
            a23[b] = add2(a23[b], shfl_down16_b64(a23[b]));
        }

        // pre-reduced partials -> red[p][kq2][b][4cq..4cq+3] (lanes < 16)
        float* rp = red + p * RED16_ELEMS;
        if (is_lo) {
#pragma unroll
            for (int b = 0; b < 4; ++b) {
                ulonglong2 v;
                v.x = a01[b];
                v.y = a23[b];
                *reinterpret_cast<ulonglong2*>(
                    &rp[(kq2 * BATCH_PER_CL + b) * COLS_PER_CTA + cq * 4]) = v;
            }
        }
        __syncthreads();   // the ONLY block barrier per step

        // Housekeeping (parallel, thread r = 0..7): re-arm full[p][r], then
        // credit CTA r's empty[p]; per-thread order is the protocol order.
        if (is_hk) {
            if (t > 0)
                MBAR_EXPECT_TX(smem_u32 + MB_FULL(p, tid), CHUNK_TX_BYTES);
            MBAR_ARRIVE_REMOTE(rbase[tid] + MB_EMPTY(p));
        }

        if (is_red) {
            // 16-way reduce, 4 parallel chains
            float s0 = xw, s1 = 0.f, s2 = 0.f, s3 = 0.f;
#pragma unroll
            for (int qd = 0; qd < 4; ++qd) {
                s0 += rp[((4 * qd + 0) * BATCH_PER_CL + fb) * COLS_PER_CTA + fc];
                s1 += rp[((4 * qd + 1) * BATCH_PER_CL + fb) * COLS_PER_CTA + fc];
                s2 += rp[((4 * qd + 2) * BATCH_PER_CL + fb) * COLS_PER_CTA + fc];
                s3 += rp[((4 * qd + 3) * BATCH_PER_CL + fb) * COLS_PER_CTA + fc];
            }
            float s = (s0 + s1) + (s2 + s3);
            float r;
            asm("tanh.approx.f32 %0, %1;" : "=f"(r) : "f"(s));
            outp[(size_t)t * HH] = r;

            if (t + 1 < TT) {
                // pair adjacent columns for 8-byte remote stores
                float rn = __shfl_down_sync(0xFFFFFFFFu, r, 1);
                if (is_store) {
                    unsigned long long v = pack2(r, rn);
                    // buffer q last read at t-1; at t==0 never read (R5 lesson)
                    if (t > 0) {
                        mbar_wait_parity(smem_u32 + MB_EMPTY(q), (uint32_t)pe[q]);
                        pe[q] ^= 1;
                    }
                    const uint32_t off =
                        (uint32_t)((q * BATCH_PER_CL + fb) * HH + jg) * 4u;
                    const uint32_t mboff = (uint32_t)MB_FULL(q, (int)rank);
#pragma unroll
                    for (int pp = 0; pp < CLUSTER; ++pp)
                        st_async_b64(rbase[pp] + off, v, rbase[pp] + mboff);
                }
            }
        }
        // no trailing barrier: red is double-buffered; cross-step ordering
        // guaranteed by bar(t) between reduce-read(t-1) and STS(t+1).
    }

    // drain before exit
    asm volatile("barrier.cluster.arrive.aligned;\n\t"
                 "barrier.cluster.wait.aligned;" ::: "memory");
}

// ---------------------------------------------------------------------------
// Launch
// ---------------------------------------------------------------------------
extern "C" void kernel_launch(void* const* d_in, const int* in_sizes, int n_in,
                              void* d_out, int out_size) {
    const float* x  = (const float*)d_in[0];
    const float* h0 = (const float*)d_in[1];
    const float* Wx = (const float*)d_in[2];
    const float* Wh = (const float*)d_in[3];
    const float* b  = (const float*)d_in[4];
    float* out = (float*)d_out;

    (void)in_sizes; (void)n_in; (void)out_size;

    dim3 gridA(HH / BN, MM / BM);
    gemm_xwx_kernel<<<gridA, 256>>>(x, Wx, b, out);

    cudaFuncSetAttribute(rnn_cluster_kernel,
                         cudaFuncAttributeMaxDynamicSharedMemorySize,
                         RNN_SMEM_BYTES);
    rnn_cluster_kernel<<<NCTA, 512, RNN_SMEM_BYTES>>>(h0, Wh, out);
}

// round 11
// speedup vs baseline: 1.0818x; 1.0818x over previous
#include <cuda_runtime.h>
#include <cuda_bf16.h>
#include <math.h>
#include <stdint.h>

// Problem constants: N=64, T=512, D=512, H=512, fp32
#define NB   64
#define TT   512
#define DD   512
#define HH   512
#define MM   (NB * TT)

// ---------------------------------------------------------------------------
// f32x2 packed-math helpers
// ---------------------------------------------------------------------------
__device__ __forceinline__ void ffma2(unsigned long long& acc,
                                      unsigned long long a,
                                      unsigned long long b) {
    asm("fma.rn.f32x2 %0, %1, %2, %0;" : "+l"(acc) : "l"(a), "l"(b));
}
__device__ __forceinline__ unsigned long long add2(unsigned long long a,
                                                   unsigned long long b) {
    unsigned long long r;
    asm("add.rn.f32x2 %0, %1, %2;" : "=l"(r) : "l"(a), "l"(b));
    return r;
}
__device__ __forceinline__ unsigned long long pack_dup(float v) {
    unsigned long long r;
    unsigned u = __float_as_uint(v);
    asm("mov.b64 %0, {%1, %1};" : "=l"(r) : "r"(u));
    return r;
}
__device__ __forceinline__ unsigned long long pack2(float lo, float hi) {
    unsigned long long r;
    asm("mov.b64 %0, {%1, %2};" : "=l"(r) : "f"(lo), "f"(hi));
    return r;
}

// mbarrier helpers -----------------------------------------------------------
#define MBAR_INIT(addr, cnt) \
    asm volatile("mbarrier.init.shared.b64 [%0], %1;" :: "r"(addr), "r"(cnt) : "memory")
#define MBAR_EXPECT_TX(addr, bytes) \
    asm volatile("mbarrier.arrive.expect_tx.shared.b64 _, [%0], %1;" \
                 :: "r"(addr), "r"(bytes) : "memory")

__device__ __forceinline__ void mbar_wait_parity(uint32_t mbar, uint32_t parity) {
    asm volatile(
        "{\n\t"
        ".reg .pred P;\n\t"
        "WL_%=:\n\t"
        "mbarrier.try_wait.parity.acquire.cluster.shared::cta.b64 P, [%0], %1, 0x989680;\n\t"
        "@P bra WD_%=;\n\t"
        "bra WL_%=;\n\t"
        "WD_%=:\n\t"
        "}" :: "r"(mbar), "r"(parity) : "memory");
}

__device__ __forceinline__ void st_async_b64(uint32_t raddr, unsigned long long v,
                                             uint32_t rmbar) {
    asm volatile(
        "st.async.shared::cluster.mbarrier::complete_tx::bytes.b64 [%0], %1, [%2];"
        :: "r"(raddr), "l"(v), "r"(rmbar) : "memory");
}

__device__ __forceinline__ unsigned long long shfl_down16_b64(unsigned long long v) {
    unsigned lo = (unsigned)(v & 0xFFFFFFFFULL);
    unsigned hi = (unsigned)(v >> 32);
    lo = __shfl_down_sync(0xFFFFFFFFu, lo, 16);
    hi = __shfl_down_sync(0xFFFFFFFFu, hi, 16);
    return ((unsigned long long)hi << 32) | lo;
}

// ---------------------------------------------------------------------------
// Kernel A: xwx = x @ Wx + b  (into d_out), FFMA2 SGEMM (unchanged)
// ---------------------------------------------------------------------------
#define BM 128
#define BN 128
#define BK 8

__global__ __launch_bounds__(256) void gemm_xwx_kernel(
    const float* __restrict__ X,
    const float* __restrict__ Wx,
    const float* __restrict__ bias,
    float* __restrict__ out)
{
    __shared__ float2 Asd[BK][BM];
    __shared__ float  Bs[BK][BN];

    const int tid = threadIdx.x;
    const int m0 = blockIdx.y * BM;
    const int n0 = blockIdx.x * BN;

    const int arow = tid >> 1;
    const int acol = (tid & 1) * 4;
    const int brow = tid >> 5;
    const int bcol = (tid & 31) * 4;

    const int ty = tid >> 4;
    const int tx = tid & 15;

    unsigned long long acc2[8][4];
#pragma unroll
    for (int i = 0; i < 8; ++i)
#pragma unroll
        for (int j = 0; j < 4; ++j) acc2[i][j] = 0ULL;

    for (int k0 = 0; k0 < DD; k0 += BK) {
        float4 av = *reinterpret_cast<const float4*>(
            X + (size_t)(m0 + arow) * DD + k0 + acol);
        float4 bv = *reinterpret_cast<const float4*>(
            Wx + (size_t)(k0 + brow) * HH + n0 + bcol);

        Asd[acol + 0][arow] = make_float2(av.x, av.x);
        Asd[acol + 1][arow] = make_float2(av.y, av.y);
        Asd[acol + 2][arow] = make_float2(av.z, av.z);
        Asd[acol + 3][arow] = make_float2(av.w, av.w);
        *reinterpret_cast<float4*>(&Bs[brow][bcol]) = bv;
        __syncthreads();

#pragma unroll
        for (int k = 0; k < BK; ++k) {
            unsigned long long a2[8], b2[4];
            ulonglong2 t0 = *reinterpret_cast<const ulonglong2*>(&Bs[k][tx * 8]);
            ulonglong2 t1 = *reinterpret_cast<const ulonglong2*>(&Bs[k][tx * 8 + 4]);
            b2[0] = t0.x; b2[1] = t0.y; b2[2] = t1.x; b2[3] = t1.y;
#pragma unroll
            for (int i = 0; i < 8; ++i)
                a2[i] = *reinterpret_cast<const unsigned long long*>(&Asd[k][ty * 8 + i]);
#pragma unroll
            for (int i = 0; i < 8; ++i)
#pragma unroll
                for (int j = 0; j < 4; ++j)
                    ffma2(acc2[i][j], a2[i], b2[j]);
        }
        __syncthreads();
    }

    unsigned long long bb2[4];
    {
        ulonglong2 t0 = *reinterpret_cast<const ulonglong2*>(bias + n0 + tx * 8);
        ulonglong2 t1 = *reinterpret_cast<const ulonglong2*>(bias + n0 + tx * 8 + 4);
        bb2[0] = t0.x; bb2[1] = t0.y; bb2[2] = t1.x; bb2[3] = t1.y;
    }
#pragma unroll
    for (int i = 0; i < 8; ++i) {
        float* orow = out + (size_t)(m0 + ty * 8 + i) * HH + n0 + tx * 8;
        ulonglong2 v0, v1;
        v0.x = add2(acc2[i][0], bb2[0]);
        v0.y = add2(acc2[i][1], bb2[1]);
        v1.x = add2(acc2[i][2], bb2[2]);
        v1.y = add2(acc2[i][3], bb2[3]);
        *reinterpret_cast<ulonglong2*>(orow)     = v0;
        *reinterpret_cast<ulonglong2*>(orow + 4) = v1;
    }
}

// ---------------------------------------------------------------------------
// Kernel B: cluster recurrence.
//   NEW vs R9: EMPTY BARRIERS DELETED. The anti-dependency they enforced
//   (writer of buffer q must follow all readers of q) is already implied by
//   the full-barrier chain:
//     X-store-to-Y.q @t  >  X-bar(t)  >  X got Y's chunk @t
//                        >  Y-stored @t-1  >  Y-bar(t-1)  >  Y-read-q done.
//   Re-arm obligation moves to an elected consumer thread right after its
//   full-wait passes: arm < X-bar(t) < X-store < Y-bar(t+1) < Y-next-store,
//   so the arm always precedes the next incoming fill. Producer path after
//   reduce is now wait-free: tanh -> STG -> shfl -> 8x st.async.
// ---------------------------------------------------------------------------
#define CLUSTER       8
#define NCTA          128
#define BATCH_PER_CL  4
#define COLS_PER_CTA  64

#define HBUF_ELEMS  (2 * BATCH_PER_CL * HH)              // 4096 floats (16 KB)
#define RED16_ELEMS (16 * BATCH_PER_CL * COLS_PER_CTA)   // 4096 floats (16 KB)
#define MBAR_OFF    ((HBUF_ELEMS + 2 * RED16_ELEMS) * 4) // 49152 bytes
// mbar layout: full[2][8] at +0..128 (stride 8)
#define MB_FULL(p, r) (MBAR_OFF + ((p) * 8 + (r)) * 8)
#define RNN_SMEM_BYTES (MBAR_OFF + 128)

#define CHUNK_TX_BYTES 1024   // 128 producer threads x 8 B land per peer chunk

__global__ __launch_bounds__(512, 1) __cluster_dims__(CLUSTER, 1, 1)
void rnn_cluster_kernel(const float* __restrict__ h0,
                        const float* __restrict__ Wh,
                        float* __restrict__ out)
{
    extern __shared__ float smem[];
    float* hbuf = smem;                       // [2][4][HH]
    float* red  = smem + HBUF_ELEMS;          // [2][16][4][64]

    const int tid = threadIdx.x;
    uint32_t rank;
    asm("mov.u32 %0, %%cluster_ctarank;" : "=r"(rank));
    const int cid = blockIdx.x >> 3;
    const int b0  = cid * BATCH_PER_CL;

    const int kq    = tid >> 4;          // 0..31
    const int cq    = tid & 15;          // 0..15
    const int kbase = kq * 16;
    const int kq2   = tid >> 5;          // warp id 0..15
    const int chunk = tid >> 6;          // 0..7: source rank my warp consumes
    const int jg0   = (int)rank * COLS_PER_CTA + cq * 4;

    // ---- Wh slice -> registers (once) ----
    unsigned long long w01[16], w23[16];
#pragma unroll
    for (int kk = 0; kk < 16; ++kk) {
        ulonglong2 v = *reinterpret_cast<const ulonglong2*>(
            Wh + (size_t)(kbase + kk) * HH + jg0);
        w01[kk] = v.x;
        w23[kk] = v.y;
    }

    uint32_t smem_u32;
    asm("{ .reg .u64 t; cvta.to.shared.u64 t, %1; cvt.u32.u64 %0, t; }"
        : "=r"(smem_u32) : "l"(smem));

    // ---- init: mbarriers + h0 into buffer 0 ----
    if (tid == 0) {
#pragma unroll
        for (int r = 0; r < CLUSTER; ++r) {
            MBAR_INIT(smem_u32 + MB_FULL(0, r), 1);
            MBAR_INIT(smem_u32 + MB_FULL(1, r), 1);
            MBAR_EXPECT_TX(smem_u32 + MB_FULL(0, r), CHUNK_TX_BYTES);
            MBAR_EXPECT_TX(smem_u32 + MB_FULL(1, r), CHUNK_TX_BYTES);
        }
    }
    for (int idx = tid; idx < BATCH_PER_CL * HH; idx += 512)
        hbuf[idx] = h0[(size_t)b0 * HH + idx];
    __syncthreads();
    asm volatile("barrier.cluster.arrive.aligned;\n\t"
                 "barrier.cluster.wait.aligned;" ::: "memory");

    // peer smem base addresses (mapa once)
    uint32_t rbase[CLUSTER];
#pragma unroll
    for (int p = 0; p < CLUSTER; ++p)
        asm("mapa.shared::cluster.u32 %0, %1, %2;"
            : "=r"(rbase[p]) : "r"(smem_u32), "r"(p));

    // output-stage mapping (threads < 256)
    const int fb = (tid >> 6) & 3;
    const int fc = tid & 63;
    const int jg = (int)rank * COLS_PER_CTA + fc;
    float* outp = out + ((size_t)(b0 + fb) * TT) * HH + jg;
    const bool is_red   = (tid < 256);
    const bool is_store = (tid < 256) && ((tid & 1) == 0);
    const bool is_arm   = ((tid & 63) == 0);   // one re-armer per chunk
    const bool is_lo    = ((tid & 16) == 0);   // lane < 16 within warp

    int pf[2] = {0, 0};   // per-warp parity for full[buf][chunk]

#pragma unroll 2
    for (int t = 0; t < TT; ++t) {
        const int p = t & 1;
        const int q = p ^ 1;

        // prefetch xwx for this step (independent of h)
        float xw = 0.0f;
        if (is_red) xw = outp[(size_t)t * HH];

        // wait only for MY chunk of h_t (produced by CTA `chunk`); then the
        // elected thread immediately re-arms this barrier for its next fill.
        if (t > 0) {
            mbar_wait_parity(smem_u32 + MB_FULL(p, chunk), (uint32_t)pf[p]);
            pf[p] ^= 1;
            if (is_arm)
                MBAR_EXPECT_TX(smem_u32 + MB_FULL(p, chunk), CHUNK_TX_BYTES);
        }

        const float* hc = hbuf + p * (BATCH_PER_CL * HH);
        unsigned long long a01[4] = {0ULL, 0ULL, 0ULL, 0ULL};
        unsigned long long a23[4] = {0ULL, 0ULL, 0ULL, 0ULL};

#pragma unroll
        for (int kk4 = 0; kk4 < 4; ++kk4) {
            const int k = kbase + kk4 * 4;
#pragma unroll
            for (int b = 0; b < 4; ++b) {
                float4 hv = *reinterpret_cast<const float4*>(&hc[b * HH + k]);
                unsigned long long hh;
                hh = pack_dup(hv.x);
                ffma2(a01[b], hh, w01[kk4 * 4 + 0]);
                ffma2(a23[b], hh, w23[kk4 * 4 + 0]);
                hh = pack_dup(hv.y);
                ffma2(a01[b], hh, w01[kk4 * 4 + 1]);
                ffma2(a23[b], hh, w23[kk4 * 4 + 1]);
                hh = pack_dup(hv.z);
                ffma2(a01[b], hh, w01[kk4 * 4 + 2]);
                ffma2(a23[b], hh, w23[kk4 * 4 + 2]);
                hh = pack_dup(hv.w);
                ffma2(a01[b], hh, w01[kk4 * 4 + 3]);
                ffma2(a23[b], hh, w23[kk4 * 4 + 3]);
            }
        }

        // warp pre-reduce: lane L += lane L+16 (kq pair, same cols)
#pragma unroll
        for (int b = 0; b < 4; ++b) {
            a01[b] = add2(a01[b], shfl_down16_b64(a01[b]));
            a23[b] = add2(a23[b], shfl_down16_b64(a23[b]));
        }

        // pre-reduced partials -> red[p][kq2][b][4cq..4cq+3] (lanes < 16)
        float* rp = red + p * RED16_ELEMS;
        if (is_lo) {
#pragma unroll
            for (int b = 0; b < 4; ++b) {
                ulonglong2 v;
                v.x = a01[b];
                v.y = a23[b];
                *reinterpret_cast<ulonglong2*>(
                    &rp[(kq2 * BATCH_PER_CL + b) * COLS_PER_CTA + cq * 4]) = v;
            }
        }
        __syncthreads();   // the ONLY block barrier per step

        if (is_red) {
            // 16-way reduce, 4 parallel chains
            float s0 = xw, s1 = 0.f, s2 = 0.f, s3 = 0.f;
#pragma unroll
            for (int qd = 0; qd < 4; ++qd) {
                s0 += rp[((4 * qd + 0) * BATCH_PER_CL + fb) * COLS_PER_CTA + fc];
                s1 += rp[((4 * qd + 1) * BATCH_PER_CL + fb) * COLS_PER_CTA + fc];
                s2 += rp[((4 * qd + 2) * BATCH_PER_CL + fb) * COLS_PER_CTA + fc];
                s3 += rp[((4 * qd + 3) * BATCH_PER_CL + fb) * COLS_PER_CTA + fc];
            }
            float s = (s0 + s1) + (s2 + s3);
            float r;
            asm("tanh.approx.f32 %0, %1;" : "=f"(r) : "f"(s));
            outp[(size_t)t * HH] = r;

            if (t + 1 < TT) {
                // pair adjacent columns for 8-byte remote stores; WAIT-FREE:
                // buffer-q readers are ordered behind us by the full-barrier
                // causal chain (see header comment).
                float rn = __shfl_down_sync(0xFFFFFFFFu, r, 1);
                if (is_store) {
                    unsigned long long v = pack2(r, rn);
                    const uint32_t off =
                        (uint32_t)((q * BATCH_PER_CL + fb) * HH + jg) * 4u;
                    const uint32_t mboff = (uint32_t)MB_FULL(q, (int)rank);
#pragma unroll
                    for (int pp = 0; pp < CLUSTER; ++pp)
                        st_async_b64(rbase[pp] + off, v, rbase[pp] + mboff);
                }
            }
        }
        // no trailing barrier: red is double-buffered; cross-step ordering
        // guaranteed by bar(t) between reduce-read(t-1) and STS(t+1).
    }

    // drain before exit
    asm volatile("barrier.cluster.arrive.aligned;\n\t"
                 "barrier.cluster.wait.aligned;" ::: "memory");
}

// ---------------------------------------------------------------------------
// Launch
// ---------------------------------------------------------------------------
extern "C" void kernel_launch(void* const* d_in, const int* in_sizes, int n_in,
                              void* d_out, int out_size) {
    const float* x  = (const float*)d_in[0];
    const float* h0 = (const float*)d_in[1];
    const float* Wx = (const float*)d_in[2];
    const float* Wh = (const float*)d_in[3];
    const float* b  = (const float*)d_in[4];
    float* out = (float*)d_out;

    (void)in_sizes; (void)n_in; (void)out_size;

    dim3 gridA(HH / BN, MM / BM);
    gemm_xwx_kernel<<<gridA, 256>>>(x, Wx, b, out);

    cudaFuncSetAttribute(rnn_cluster_kernel,
                         cudaFuncAttributeMaxDynamicSharedMemorySize,
                         RNN_SMEM_BYTES);
    rnn_cluster_kernel<<<NCTA, 512, RNN_SMEM_BYTES>>>(h0, Wh, out);
}